// round 2
// baseline (speedup 1.0000x reference)
#include <cuda_runtime.h>
#include <math.h>

#define BATCH   128
#define T_STEPS 512
#define HID     1024
#define OUTF    128
#define GRID    128
#define NTHR    256
#define UPC     8      // hidden units per CTA
#define KB      32     // k-block staged per iteration
#define NB      (HID / KB)
#define AS_STRIDE 34   // padded row stride (floats) for h tile in smem
#define ASB     (BATCH * AS_STRIDE)   // floats per staging buffer

// Persistent state (no allocations allowed)
__device__ float g_h[2][BATCH * HID];
__device__ unsigned int g_arrive;
__device__ volatile unsigned int g_epoch;

__device__ __forceinline__ void fma2(float2& c, const float2 a, const float2 b) {
    asm("fma.rn.f32x2 %0, %1, %2, %0;"
        : "+l"(reinterpret_cast<unsigned long long&>(c))
        : "l"(reinterpret_cast<const unsigned long long&>(a)),
          "l"(reinterpret_cast<const unsigned long long&>(b)));
}

__device__ __forceinline__ float sigf(float x) { return 1.0f / (1.0f + expf(-x)); }

__global__ void reset_kernel() {
    g_arrive = 0;
    g_epoch = 0;
}

__global__ void __launch_bounds__(NTHR, 1)
lstm_kernel(const float* __restrict__ y_hist,
            const float* __restrict__ W_ih,
            const float* __restrict__ W_hh,
            const float* __restrict__ b_ih,
            const float* __restrict__ b_hh,
            const float* __restrict__ fc_W,
            const float* __restrict__ fc_b,
            const float* __restrict__ h0,
            const float* __restrict__ c0,
            float* __restrict__ out)
{
    extern __shared__ float smem[];
    float* Ws = smem;            // 32*1024 floats, pair-interleaved k-major
    float* As = smem + 32 * HID; // 2 * ASB floats (double-buffered h staging)

    const int tid = threadIdx.x;
    const int tx  = tid & 7;     // unit within CTA (0..7)
    const int ty  = tid >> 3;    // batch-quad (0..31)
    const int n0  = blockIdx.x * UPC;
    const int n   = n0 + tx;     // this thread's hidden unit

    // ---- Load W_hh slice into smem, pair-interleaved: two consecutive k
    // adjacent per row. Ws[(k>>1)*64 + lr*2 + (k&1)], lr = u*4 + g
    // <-> global row g*HID + n0 + u. One-time cost (~128KB).
    for (int e = tid; e < 32 * HID; e += NTHR) {
        int lr = e >> 10;
        int k  = e & 1023;
        int u = lr >> 2, g = lr & 3;
        Ws[(k >> 1) * 64 + lr * 2 + (k & 1)] = W_hh[(g * HID + n0 + u) * HID + k];
    }

    // ---- Per-thread constants and cell state (registers)
    float wih[4], bb[4], c_reg[4];
#pragma unroll
    for (int g = 0; g < 4; g++) {
        wih[g] = W_ih[g * HID + n];
        bb[g]  = b_ih[g * HID + n] + b_hh[g * HID + n];
    }
#pragma unroll
    for (int j = 0; j < 4; j++)
        c_reg[j] = c0[(4 * ty + j) * HID + n];

    __syncthreads();

    // Loader mapping: 4 float4 per thread per k-block (coalesced from global h)
    int lb[4], lk[4];
#pragma unroll
    for (int i = 0; i < 4; i++) {
        int f = tid + i * NTHR;
        lb[i] = f >> 3;          // batch row
        lk[i] = (f & 7) * 4;     // k offset within block
    }

    for (int s = 0; s < T_STEPS; s++) {
        const float* hsrc = (s == 0) ? h0 : g_h[s & 1];
        float* hdst = g_h[(s + 1) & 1];

        // Prefetch this step's driving inputs early (L2 latency hidden by GEMM)
        float xv[4];
#pragma unroll
        for (int j = 0; j < 4; j++)
            xv[j] = __ldg(&y_hist[(4 * ty + j) * T_STEPS + s]);

        // Prologue: stage k-block 0, prefetch block 1
        float4 pv[4];
#pragma unroll
        for (int i = 0; i < 4; i++)
            pv[i] = *reinterpret_cast<const float4*>(hsrc + lb[i] * HID + lk[i]);
#pragma unroll
        for (int i = 0; i < 4; i++) {
            float* p = As + lb[i] * AS_STRIDE + lk[i];
            p[0] = pv[i].x; p[1] = pv[i].y; p[2] = pv[i].z; p[3] = pv[i].w;
        }
        {
            const float* gp = hsrc + KB;
#pragma unroll
            for (int i = 0; i < 4; i++)
                pv[i] = *reinterpret_cast<const float4*>(gp + lb[i] * HID + lk[i]);
        }

        float2 acc[4][4];
#pragma unroll
        for (int j = 0; j < 4; j++)
#pragma unroll
            for (int g = 0; g < 4; g++)
                acc[j][g] = make_float2(0.f, 0.f);

        __syncthreads();

        for (int kb = 0; kb < NB; kb++) {
            const float* cur = As + (kb & 1) * ASB;
            // Stage block kb+1 into the other buffer; prefetch block kb+2.
            if (kb + 1 < NB) {
                float* nxt = As + ((kb + 1) & 1) * ASB;
#pragma unroll
                for (int i = 0; i < 4; i++) {
                    float* p = nxt + lb[i] * AS_STRIDE + lk[i];
                    p[0] = pv[i].x; p[1] = pv[i].y; p[2] = pv[i].z; p[3] = pv[i].w;
                }
                if (kb + 2 < NB) {
                    const float* gp = hsrc + (kb + 2) * KB;
#pragma unroll
                    for (int i = 0; i < 4; i++)
                        pv[i] = *reinterpret_cast<const float4*>(gp + lb[i] * HID + lk[i]);
                }
            }
            // Compute on current buffer
            const float* wbase = Ws + ((kb * KB) >> 1) * 64 + tx * 8;
#pragma unroll
            for (int kk = 0; kk < KB; kk += 2) {
                float4 w01 = *reinterpret_cast<const float4*>(wbase + (kk >> 1) * 64);
                float4 w23 = *reinterpret_cast<const float4*>(wbase + (kk >> 1) * 64 + 4);
                float2 wv[4];
                wv[0] = make_float2(w01.x, w01.y);
                wv[1] = make_float2(w01.z, w01.w);
                wv[2] = make_float2(w23.x, w23.y);
                wv[3] = make_float2(w23.z, w23.w);
#pragma unroll
                for (int j = 0; j < 4; j++) {
                    float2 av = *reinterpret_cast<const float2*>(
                        cur + (4 * ty + j) * AS_STRIDE + kk);
#pragma unroll
                    for (int g = 0; g < 4; g++)
                        fma2(acc[j][g], av, wv[g]);
                }
            }
            __syncthreads();
        }

        // ---- Cell update epilogue (gates i,f,g,o for 4 batches, one unit)
#pragma unroll
        for (int j = 0; j < 4; j++) {
            int b = 4 * ty + j;
            float gi = acc[j][0].x + acc[j][0].y + xv[j] * wih[0] + bb[0];
            float gf = acc[j][1].x + acc[j][1].y + xv[j] * wih[1] + bb[1];
            float gg = acc[j][2].x + acc[j][2].y + xv[j] * wih[2] + bb[2];
            float go = acc[j][3].x + acc[j][3].y + xv[j] * wih[3] + bb[3];
            float cn = sigf(gf) * c_reg[j] + sigf(gi) * tanhf(gg);
            c_reg[j] = cn;
            hdst[b * HID + n] = sigf(go) * tanhf(cn);
        }

        // ---- Grid barrier (sense via monotonically increasing epoch)
        __syncthreads();
        if (tid == 0) {
            __threadfence();
            unsigned target = (unsigned)(s + 1);
            unsigned a = atomicAdd(&g_arrive, 1u);
            if (a == GRID - 1) {
                g_arrive = 0;
                __threadfence();
                g_epoch = target;
            } else {
                while (g_epoch < target) __nanosleep(64);
            }
            __threadfence();
        }
        __syncthreads();
    }

    // ---- Final FC: CTA b computes out[b, 0..127]. h_T is in g_h[0] (T even).
    {
        int b = blockIdx.x;
        const float* hT = g_h[0] + b * HID;
        float* hrow = As;  // reuse staging smem (>= 1024 floats)
        reinterpret_cast<float4*>(hrow)[tid] =
            reinterpret_cast<const float4*>(hT)[tid];   // 256 * float4 = 1024
        __syncthreads();
        int w = tid >> 5, lane = tid & 31;
        for (int o = w; o < OUTF; o += 8) {
            const float* fw = fc_W + o * HID;
            float sum = 0.f;
            for (int kk = lane; kk < HID; kk += 32)
                sum += hrow[kk] * __ldg(&fw[kk]);
#pragma unroll
            for (int d = 16; d; d >>= 1)
                sum += __shfl_xor_sync(0xffffffffu, sum, d);
            if (lane == 0)
                out[b * OUTF + o] = sum + fc_b[o];
        }
    }
}

extern "C" void kernel_launch(void* const* d_in, const int* in_sizes, int n_in,
                              void* d_out, int out_size)
{
    const float* y_hist = (const float*)d_in[0];
    const float* W_ih   = (const float*)d_in[1];
    const float* W_hh   = (const float*)d_in[2];
    const float* b_ih   = (const float*)d_in[3];
    const float* b_hh   = (const float*)d_in[4];
    const float* fc_W   = (const float*)d_in[5];
    const float* fc_b   = (const float*)d_in[6];
    const float* h0     = (const float*)d_in[7];
    const float* c0     = (const float*)d_in[8];
    float* out = (float*)d_out;

    const int smem_bytes = (32 * HID + 2 * ASB) * sizeof(float); // 165888
    cudaFuncSetAttribute(lstm_kernel,
                         cudaFuncAttributeMaxDynamicSharedMemorySize, smem_bytes);

    reset_kernel<<<1, 1>>>();
    lstm_kernel<<<GRID, NTHR, smem_bytes>>>(y_hist, W_ih, W_hh, b_ih, b_hh,
                                            fc_W, fc_b, h0, c0, out);
}

// round 4
// speedup vs baseline: 3.3100x; 3.3100x over previous
#include <cuda_runtime.h>
#include <cuda_bf16.h>
#include <math.h>
#include <stdint.h>

#define BATCH   128
#define T_STEPS 512
#define HID     1024
#define OUTF    128
#define GRID    128
#define NTHR    128
#define NC      32          // gate rows per CTA (8 units x 4 gates)
#define UPC     8
#define KCH     64          // k elems per chunk (128B rows)
#define NCHUNK  (HID / KCH) // 16
#define CS      34          // Csm row stride (floats)

// ---- persistent device state ----
__device__ __nv_bfloat16 g_h1[2][BATCH * HID];
__device__ __nv_bfloat16 g_h2[2][BATCH * HID];
__device__ float         g_hT[BATCH * HID];
__device__ unsigned int  g_arrive;
__device__ volatile unsigned int g_epoch;

// ---- smem layout (bytes) ----
#define OFF_BB 64                      // 32 floats: b_ih+b_hh
#define OFF_WI 192                     // 32 floats: w_ih
#define OFF_W1 1024                    // W1: 16 chunks x 4KB = 64KB
#define OFF_W2 (OFF_W1 + 65536)       // W2: 64KB
#define OFF_A  (OFF_W2 + 65536)       // A: 2 bufs x 2 parts x 16KB = 64KB
#define OFF_C  (OFF_A + 65536)        // C scratch: 128*CS*4 = 17408B
#define SMEM_BYTES (OFF_C + BATCH * CS * 4)

__device__ __forceinline__ uint32_t smem_u32(const void* p) {
    return (uint32_t)__cvta_generic_to_shared(p);
}
__device__ __forceinline__ void cp16(uint32_t s, const void* g) {
    asm volatile("cp.async.cg.shared.global [%0], [%1], 16;" :: "r"(s), "l"(g));
}
__device__ __forceinline__ void ldm4(uint32_t r[4], uint32_t addr) {
    asm volatile("ldmatrix.sync.aligned.m8n8.x4.shared.b16 {%0,%1,%2,%3}, [%4];"
                 : "=r"(r[0]), "=r"(r[1]), "=r"(r[2]), "=r"(r[3]) : "r"(addr));
}
__device__ __forceinline__ void mma16816(float c[4], const uint32_t a[4],
                                         uint32_t b0, uint32_t b1) {
    asm volatile(
        "mma.sync.aligned.m16n8k16.row.col.f32.bf16.bf16.f32 "
        "{%0,%1,%2,%3},{%4,%5,%6,%7},{%8,%9},{%0,%1,%2,%3};"
        : "+f"(c[0]), "+f"(c[1]), "+f"(c[2]), "+f"(c[3])
        : "r"(a[0]), "r"(a[1]), "r"(a[2]), "r"(a[3]), "r"(b0), "r"(b1));
}
__device__ __forceinline__ uint32_t sw128(uint32_t off) {
    return off ^ ((off >> 3) & 0x70);
}
__device__ __forceinline__ float sigf(float x) { return 1.0f / (1.0f + expf(-x)); }

__global__ void reset_kernel() { g_arrive = 0; g_epoch = 0; }

__global__ void split_h0_kernel(const float* __restrict__ h0) {
    for (int j = blockIdx.x * blockDim.x + threadIdx.x; j < BATCH * HID;
         j += gridDim.x * blockDim.x) {
        float v = h0[j];
        __nv_bfloat16 a = __float2bfloat16(v);
        __nv_bfloat16 b = __float2bfloat16(v - __bfloat162float(a));
        g_h1[0][j] = a;
        g_h2[0][j] = b;
    }
}

__global__ void __launch_bounds__(NTHR, 1)
lstm_kernel(const float* __restrict__ y_hist,
            const float* __restrict__ W_ih,
            const float* __restrict__ W_hh,
            const float* __restrict__ b_ih,
            const float* __restrict__ b_hh,
            const float* __restrict__ fc_W,
            const float* __restrict__ fc_b,
            const float* __restrict__ h0,
            const float* __restrict__ c0,
            float* __restrict__ out)
{
    extern __shared__ char smem[];
    const uint32_t sb = smem_u32(smem);
    const int tid  = threadIdx.x;
    const int wid  = tid >> 5;
    const int lane = tid & 31;
    const int n0   = blockIdx.x * UPC;
    const int b    = tid;     // batch row for epilogue (128 threads)

    // ---- One-time: W_hh slice -> bf16 hi/lo, SW128 chunk tiles in smem.
    // n-col lr = u*4+g <-> W_hh row g*HID + n0+u.
    for (int e = tid; e < NC * HID; e += NTHR) {
        int lr = e >> 10, k = e & 1023;
        int u = lr >> 2, g = lr & 3;
        float w = W_hh[(g * HID + n0 + u) * HID + k];
        __nv_bfloat16 w1 = __float2bfloat16(w);
        __nv_bfloat16 w2 = __float2bfloat16(w - __bfloat162float(w1));
        int kc  = k >> 6;
        uint32_t off = (uint32_t)(lr * 128 + (k & 63) * 2);
        uint32_t sw  = sw128(off);
        *(__nv_bfloat16*)(smem + OFF_W1 + kc * 4096 + sw) = w1;
        *(__nv_bfloat16*)(smem + OFF_W2 + kc * 4096 + sw) = w2;
    }
    for (int e = tid; e < NC; e += NTHR) {
        int u = e >> 2, g = e & 3;
        int gr = g * HID + n0 + u;
        ((float*)(smem + OFF_BB))[e] = b_ih[gr] + b_hh[gr];
        ((float*)(smem + OFF_WI))[e] = W_ih[gr];
    }
    float c_reg[UPC];
#pragma unroll
    for (int u = 0; u < UPC; u++)
        c_reg[u] = c0[b * HID + n0 + u];
    __syncthreads();

    float* Csm = (float*)(smem + OFF_C);
    const float* bbp = (const float*)(smem + OFF_BB);
    const float* wip = (const float*)(smem + OFF_WI);

    for (int s = 0; s < T_STEPS; s++) {
        const char* h1src = (const char*)g_h1[s & 1];
        const char* h2src = (const char*)g_h2[s & 1];
        float x = __ldg(&y_hist[b * T_STEPS + s]);

        // stage chunk 0 -> buf 0
#pragma unroll
        for (int part = 0; part < 2; part++) {
            const char* gp = part ? h2src : h1src;
            uint32_t abase = sb + OFF_A + part * 16384;
#pragma unroll
            for (int i = 0; i < 8; i++) {
                int f = i * NTHR + tid;
                int row = f >> 3, seg = f & 7;
                uint32_t off = (uint32_t)(row * 128 + seg * 16);
                cp16(abase + sw128(off), gp + row * 2048 + seg * 16);
            }
        }
        asm volatile("cp.async.commit_group;" ::: "memory");

        float acc[2][4][4];
#pragma unroll
        for (int mt = 0; mt < 2; mt++)
#pragma unroll
            for (int nt = 0; nt < 4; nt++)
#pragma unroll
                for (int q = 0; q < 4; q++)
                    acc[mt][nt][q] = 0.f;

        for (int kc = 0; kc < NCHUNK; kc++) {
            int buf = kc & 1;
            if (kc + 1 < NCHUNK) {
                int nb = (kc + 1) & 1;
#pragma unroll
                for (int part = 0; part < 2; part++) {
                    const char* gp = part ? h2src : h1src;
                    uint32_t abase = sb + OFF_A + (nb * 2 + part) * 16384;
#pragma unroll
                    for (int i = 0; i < 8; i++) {
                        int f = i * NTHR + tid;
                        int row = f >> 3, seg = f & 7;
                        uint32_t off = (uint32_t)(row * 128 + seg * 16);
                        cp16(abase + sw128(off),
                             gp + row * 2048 + (kc + 1) * 128 + seg * 16);
                    }
                }
                asm volatile("cp.async.commit_group;" ::: "memory");
                asm volatile("cp.async.wait_group 1;" ::: "memory");
            } else {
                asm volatile("cp.async.wait_group 0;" ::: "memory");
            }
            __syncthreads();

            const uint32_t a1b = sb + OFF_A + (buf * 2 + 0) * 16384;
            const uint32_t a2b = sb + OFF_A + (buf * 2 + 1) * 16384;
            const uint32_t w1b = sb + OFF_W1 + kc * 4096;
            const uint32_t w2b = sb + OFF_W2 + kc * 4096;

            // ldmatrix lane address components
            const int arow = lane & 15;                       // A row within m16
            const int akb  = (lane >> 4) << 4;                // A k-half (bytes)
            const int brow = (lane & 7) + ((lane & 16) >> 1); // B row within n16
            const int bkb  = (lane & 8) << 1;                 // B k-half (bytes)

#pragma unroll
            for (int t = 0; t < 4; t++) {   // 4 k-tiles of 16 per chunk
                const int kb = t * 32;
                uint32_t a1[2][4], a2[2][4], bw1[2][4], bw2[2][4];
#pragma unroll
                for (int mt = 0; mt < 2; mt++) {
                    uint32_t off = (uint32_t)((wid * 32 + mt * 16 + arow) * 128
                                              + kb + akb);
                    ldm4(a1[mt], a1b + sw128(off));
                    ldm4(a2[mt], a2b + sw128(off));
                }
#pragma unroll
                for (int np = 0; np < 2; np++) {
                    uint32_t off = (uint32_t)((np * 16 + brow) * 128 + kb + bkb);
                    ldm4(bw1[np], w1b + sw128(off));
                    ldm4(bw2[np], w2b + sw128(off));
                }
#pragma unroll
                for (int mt = 0; mt < 2; mt++)
#pragma unroll
                    for (int nt = 0; nt < 4; nt++) {
                        uint32_t b0 = bw1[nt >> 1][(nt & 1) * 2];
                        uint32_t b1 = bw1[nt >> 1][(nt & 1) * 2 + 1];
                        uint32_t c0 = bw2[nt >> 1][(nt & 1) * 2];
                        uint32_t c1 = bw2[nt >> 1][(nt & 1) * 2 + 1];
                        mma16816(acc[mt][nt], a1[mt], b0, b1);  // h1@W1
                        mma16816(acc[mt][nt], a1[mt], c0, c1);  // h1@W2
                        mma16816(acc[mt][nt], a2[mt], b0, b1);  // h2@W1
                    }
            }
            __syncthreads();   // protect buffer before next cp overwrites
        }

        // ---- C fragments -> smem scratch ----
#pragma unroll
        for (int mt = 0; mt < 2; mt++) {
            int r0 = wid * 32 + mt * 16 + (lane >> 2);
#pragma unroll
            for (int nt = 0; nt < 4; nt++) {
                int col = nt * 8 + (lane & 3) * 2;
                *(float2*)(Csm + r0 * CS + col) =
                    make_float2(acc[mt][nt][0], acc[mt][nt][1]);
                *(float2*)(Csm + (r0 + 8) * CS + col) =
                    make_float2(acc[mt][nt][2], acc[mt][nt][3]);
            }
        }
        __syncthreads();

        // ---- cell update: thread b owns batch row b, units u0..7 ----
        unsigned short h1r[UPC], h2r[UPC];
#pragma unroll
        for (int u = 0; u < UPC; u++) {
            float gi = Csm[b * CS + 4 * u + 0] + x * wip[4 * u + 0] + bbp[4 * u + 0];
            float gf = Csm[b * CS + 4 * u + 1] + x * wip[4 * u + 1] + bbp[4 * u + 1];
            float gg = Csm[b * CS + 4 * u + 2] + x * wip[4 * u + 2] + bbp[4 * u + 2];
            float go = Csm[b * CS + 4 * u + 3] + x * wip[4 * u + 3] + bbp[4 * u + 3];
            float cn = sigf(gf) * c_reg[u] + sigf(gi) * tanhf(gg);
            c_reg[u] = cn;
            float hv = sigf(go) * tanhf(cn);
            __nv_bfloat16 hv1 = __float2bfloat16(hv);
            __nv_bfloat16 hv2 = __float2bfloat16(hv - __bfloat162float(hv1));
            h1r[u] = __bfloat16_as_ushort(hv1);
            h2r[u] = __bfloat16_as_ushort(hv2);
            if (s == T_STEPS - 1) g_hT[b * HID + n0 + u] = hv;
        }
        uint32_t p1[4], p2[4];
#pragma unroll
        for (int q = 0; q < 4; q++) {
            p1[q] = (uint32_t)h1r[2 * q] | ((uint32_t)h1r[2 * q + 1] << 16);
            p2[q] = (uint32_t)h2r[2 * q] | ((uint32_t)h2r[2 * q + 1] << 16);
        }
        *(uint4*)(&g_h1[(s + 1) & 1][b * HID + n0]) = make_uint4(p1[0], p1[1], p1[2], p1[3]);
        *(uint4*)(&g_h2[(s + 1) & 1][b * HID + n0]) = make_uint4(p2[0], p2[1], p2[2], p2[3]);

        // ---- grid barrier ----
        __syncthreads();
        if (tid == 0) {
            __threadfence();
            unsigned target = (unsigned)(s + 1);
            unsigned a = atomicAdd(&g_arrive, 1u);
            if (a == GRID - 1) {
                g_arrive = 0;
                __threadfence();
                g_epoch = target;
            } else {
                while (g_epoch < target) __nanosleep(32);
            }
            __threadfence();
        }
        __syncthreads();
    }

    // ---- Final FC: CTA bb computes out[bb, 0..127] ----
    {
        int bb = blockIdx.x;
        float* hrow = (float*)(smem + OFF_A);
#pragma unroll
        for (int i = 0; i < 2; i++)
            ((float4*)hrow)[tid + i * NTHR] =
                ((const float4*)(g_hT + bb * HID))[tid + i * NTHR];
        __syncthreads();
        for (int o = wid; o < OUTF; o += 4) {
            const float* fw = fc_W + o * HID;
            float sum = 0.f;
            for (int kk = lane; kk < HID; kk += 32)
                sum += hrow[kk] * __ldg(&fw[kk]);
#pragma unroll
            for (int dd = 16; dd; dd >>= 1)
                sum += __shfl_xor_sync(0xffffffffu, sum, dd);
            if (lane == 0)
                out[bb * OUTF + o] = sum + fc_b[o];
        }
    }
}

extern "C" void kernel_launch(void* const* d_in, const int* in_sizes, int n_in,
                              void* d_out, int out_size)
{
    const float* y_hist = (const float*)d_in[0];
    const float* W_ih   = (const float*)d_in[1];
    const float* W_hh   = (const float*)d_in[2];
    const float* b_ih   = (const float*)d_in[3];
    const float* b_hh   = (const float*)d_in[4];
    const float* fc_W   = (const float*)d_in[5];
    const float* fc_b   = (const float*)d_in[6];
    const float* h0     = (const float*)d_in[7];
    const float* c0     = (const float*)d_in[8];
    float* out = (float*)d_out;

    cudaFuncSetAttribute(lstm_kernel,
                         cudaFuncAttributeMaxDynamicSharedMemorySize, SMEM_BYTES);

    reset_kernel<<<1, 1>>>();
    split_h0_kernel<<<128, 256>>>(h0);
    lstm_kernel<<<GRID, NTHR, SMEM_BYTES>>>(y_hist, W_ih, W_hh, b_ih, b_hh,
                                            fc_W, fc_b, h0, c0, out);
}

// round 5
// speedup vs baseline: 3.3802x; 1.0212x over previous
#include <cuda_runtime.h>
#include <cuda_bf16.h>
#include <math.h>
#include <stdint.h>

#define BATCH   128
#define T_STEPS 512
#define HID     1024
#define OUTF    128
#define GRID    128
#define NTHR    256
#define NC      32          // gate rows per CTA (8 units x 4 gates)
#define UPC     8
#define KCH     64          // k elems per chunk (128B rows)
#define NCHUNK  (HID / KCH) // 16
#define CS      34          // Csm row stride (floats)

// ---- persistent device state (zero-init at module load; barrier design keeps
//      it returning to the zero state after every launch) ----
__device__ __nv_bfloat16 g_h1[2][BATCH * HID];
__device__ __nv_bfloat16 g_h2[2][BATCH * HID];
__device__ float         g_hT[BATCH * HID];
__device__ unsigned int  g_arrive;
__device__ volatile unsigned int g_sense;

// ---- smem layout (bytes) ----
#define OFF_BB 64                      // 32 floats: b_ih+b_hh
#define OFF_WI 192                     // 32 floats: w_ih
#define OFF_W1 1024                    // W1: 16 chunks x 4KB = 64KB
#define OFF_W2 (OFF_W1 + 65536)       // W2: 64KB
#define OFF_A  (OFF_W2 + 65536)       // A: 2 bufs x 2 parts x 16KB = 64KB
#define OFF_C  (OFF_A + 65536)        // C scratch: 128*CS*4 = 17408B
#define SMEM_BYTES (OFF_C + BATCH * CS * 4)

__device__ __forceinline__ uint32_t smem_u32(const void* p) {
    return (uint32_t)__cvta_generic_to_shared(p);
}
__device__ __forceinline__ void cp16(uint32_t s, const void* g) {
    asm volatile("cp.async.cg.shared.global [%0], [%1], 16;" :: "r"(s), "l"(g));
}
__device__ __forceinline__ void ldm4(uint32_t r[4], uint32_t addr) {
    asm volatile("ldmatrix.sync.aligned.m8n8.x4.shared.b16 {%0,%1,%2,%3}, [%4];"
                 : "=r"(r[0]), "=r"(r[1]), "=r"(r[2]), "=r"(r[3]) : "r"(addr));
}
__device__ __forceinline__ void mma16816(float c[4], const uint32_t a[4],
                                         uint32_t b0, uint32_t b1) {
    asm volatile(
        "mma.sync.aligned.m16n8k16.row.col.f32.bf16.bf16.f32 "
        "{%0,%1,%2,%3},{%4,%5,%6,%7},{%8,%9},{%0,%1,%2,%3};"
        : "+f"(c[0]), "+f"(c[1]), "+f"(c[2]), "+f"(c[3])
        : "r"(a[0]), "r"(a[1]), "r"(a[2]), "r"(a[3]), "r"(b0), "r"(b1));
}
__device__ __forceinline__ uint32_t sw128(uint32_t off) {
    return off ^ ((off >> 3) & 0x70);
}
__device__ __forceinline__ float sigf(float x) { return 1.0f / (1.0f + expf(-x)); }

// Sense-reversing grid barrier. Caller flips *local before use; an EVEN number
// of calls per launch returns g_sense to 0 (its static-init value).
__device__ __forceinline__ void grid_barrier(int tid, unsigned* local) {
    __syncthreads();
    if (tid == 0) {
        unsigned want = *local ^ 1u;
        *local = want;
        __threadfence();
        unsigned a = atomicAdd(&g_arrive, 1u);
        if (a == GRID - 1) {
            g_arrive = 0;
            __threadfence();
            g_sense = want;
        } else {
            while (g_sense != want) __nanosleep(32);
        }
        __threadfence();
    }
    __syncthreads();
}

__global__ void __launch_bounds__(NTHR, 1)
lstm_kernel(const float* __restrict__ y_hist,
            const float* __restrict__ W_ih,
            const float* __restrict__ W_hh,
            const float* __restrict__ b_ih,
            const float* __restrict__ b_hh,
            const float* __restrict__ fc_W,
            const float* __restrict__ fc_b,
            const float* __restrict__ h0,
            const float* __restrict__ c0,
            float* __restrict__ out)
{
    extern __shared__ char smem[];
    const uint32_t sb = smem_u32(smem);
    const int tid  = threadIdx.x;
    const int wid  = tid >> 5;
    const int lane = tid & 31;
    const int n0   = blockIdx.x * UPC;
    const int b    = tid & 127;        // batch row for epilogue
    const int half = tid >> 7;         // which 4 units this thread updates
    unsigned bar_sense = 0;

    // ---- Split h0 for OUR batch row into bf16 hi/lo (grid covers all rows) ----
    {
        int bb = blockIdx.x;
        for (int e = tid; e < HID; e += NTHR) {
            float v = h0[bb * HID + e];
            __nv_bfloat16 a = __float2bfloat16(v);
            __nv_bfloat16 r = __float2bfloat16(v - __bfloat162float(a));
            g_h1[0][bb * HID + e] = a;
            g_h2[0][bb * HID + e] = r;
        }
    }

    // ---- One-time: W_hh slice -> bf16 hi/lo, SW128 chunk tiles in smem ----
    for (int e = tid; e < NC * HID; e += NTHR) {
        int lr = e >> 10, k = e & 1023;
        int u = lr >> 2, g = lr & 3;
        float w = W_hh[(g * HID + n0 + u) * HID + k];
        __nv_bfloat16 w1 = __float2bfloat16(w);
        __nv_bfloat16 w2 = __float2bfloat16(w - __bfloat162float(w1));
        int kc  = k >> 6;
        uint32_t off = (uint32_t)(lr * 128 + (k & 63) * 2);
        uint32_t sw  = sw128(off);
        *(__nv_bfloat16*)(smem + OFF_W1 + kc * 4096 + sw) = w1;
        *(__nv_bfloat16*)(smem + OFF_W2 + kc * 4096 + sw) = w2;
    }
    for (int e = tid; e < NC; e += NTHR) {
        int u = e >> 2, g = e & 3;
        int gr = g * HID + n0 + u;
        ((float*)(smem + OFF_BB))[e] = b_ih[gr] + b_hh[gr];
        ((float*)(smem + OFF_WI))[e] = W_ih[gr];
    }
    float c_reg[4];
#pragma unroll
    for (int u = 0; u < 4; u++)
        c_reg[u] = c0[b * HID + n0 + half * 4 + u];

    // barrier #1: h0 split visible grid-wide (also covers smem W via syncthreads)
    grid_barrier(tid, &bar_sense);

    float* Csm = (float*)(smem + OFF_C);
    const float* bbp = (const float*)(smem + OFF_BB);
    const float* wip = (const float*)(smem + OFF_WI);

    for (int s = 0; s < T_STEPS; s++) {
        const char* h1src = (const char*)g_h1[s & 1];
        const char* h2src = (const char*)g_h2[s & 1];
        float x = __ldg(&y_hist[b * T_STEPS + s]);

        // stage chunk 0 -> buf 0 (4 cp16 per part per thread)
#pragma unroll
        for (int part = 0; part < 2; part++) {
            const char* gp = part ? h2src : h1src;
            uint32_t abase = sb + OFF_A + part * 16384;
#pragma unroll
            for (int i = 0; i < 4; i++) {
                int f = i * NTHR + tid;
                int row = f >> 3, seg = f & 7;
                uint32_t off = (uint32_t)(row * 128 + seg * 16);
                cp16(abase + sw128(off), gp + row * 2048 + seg * 16);
            }
        }
        asm volatile("cp.async.commit_group;" ::: "memory");

        float acc[4][4];
#pragma unroll
        for (int nt = 0; nt < 4; nt++)
#pragma unroll
            for (int q = 0; q < 4; q++)
                acc[nt][q] = 0.f;

        for (int kc = 0; kc < NCHUNK; kc++) {
            int buf = kc & 1;
            if (kc + 1 < NCHUNK) {
                int nb = (kc + 1) & 1;
#pragma unroll
                for (int part = 0; part < 2; part++) {
                    const char* gp = part ? h2src : h1src;
                    uint32_t abase = sb + OFF_A + (nb * 2 + part) * 16384;
#pragma unroll
                    for (int i = 0; i < 4; i++) {
                        int f = i * NTHR + tid;
                        int row = f >> 3, seg = f & 7;
                        uint32_t off = (uint32_t)(row * 128 + seg * 16);
                        cp16(abase + sw128(off),
                             gp + row * 2048 + (kc + 1) * 128 + seg * 16);
                    }
                }
                asm volatile("cp.async.commit_group;" ::: "memory");
                asm volatile("cp.async.wait_group 1;" ::: "memory");
            } else {
                asm volatile("cp.async.wait_group 0;" ::: "memory");
            }
            __syncthreads();

            const uint32_t a1b = sb + OFF_A + (buf * 2 + 0) * 16384;
            const uint32_t a2b = sb + OFF_A + (buf * 2 + 1) * 16384;
            const uint32_t w1b = sb + OFF_W1 + kc * 4096;
            const uint32_t w2b = sb + OFF_W2 + kc * 4096;

            const int arow = lane & 15;
            const int akb  = (lane >> 4) << 4;
            const int brow = (lane & 7) + ((lane & 16) >> 1);
            const int bkb  = (lane & 8) << 1;

#pragma unroll
            for (int t = 0; t < 4; t++) {   // 4 k16-tiles per chunk
                const int kb = t * 32;
                uint32_t a1[4], a2[4], bw1[2][4], bw2[2][4];
                {
                    uint32_t off = (uint32_t)((wid * 16 + arow) * 128 + kb + akb);
                    ldm4(a1, a1b + sw128(off));
                    ldm4(a2, a2b + sw128(off));
                }
#pragma unroll
                for (int np = 0; np < 2; np++) {
                    uint32_t off = (uint32_t)((np * 16 + brow) * 128 + kb + bkb);
                    ldm4(bw1[np], w1b + sw128(off));
                    ldm4(bw2[np], w2b + sw128(off));
                }
#pragma unroll
                for (int nt = 0; nt < 4; nt++) {
                    uint32_t b0 = bw1[nt >> 1][(nt & 1) * 2];
                    uint32_t b1 = bw1[nt >> 1][(nt & 1) * 2 + 1];
                    uint32_t c0f = bw2[nt >> 1][(nt & 1) * 2];
                    uint32_t c1f = bw2[nt >> 1][(nt & 1) * 2 + 1];
                    mma16816(acc[nt], a1, b0, b1);    // h1@W1
                    mma16816(acc[nt], a1, c0f, c1f);  // h1@W2
                    mma16816(acc[nt], a2, b0, b1);    // h2@W1
                }
            }
            __syncthreads();   // protect buffer before next cp overwrites
        }

        // ---- C fragments -> smem scratch (warp owns rows wid*16..+15) ----
        {
            int r0 = wid * 16 + (lane >> 2);
#pragma unroll
            for (int nt = 0; nt < 4; nt++) {
                int col = nt * 8 + (lane & 3) * 2;
                *(float2*)(Csm + r0 * CS + col) = make_float2(acc[nt][0], acc[nt][1]);
                *(float2*)(Csm + (r0 + 8) * CS + col) = make_float2(acc[nt][2], acc[nt][3]);
            }
        }
        __syncthreads();

        // ---- cell update: thread (b, half) owns batch row b, units half*4..+3 ----
        unsigned short h1r[4], h2r[4];
#pragma unroll
        for (int u = 0; u < 4; u++) {
            int ug = half * 4 + u;
            float gi = Csm[b * CS + 4 * ug + 0] + x * wip[4 * ug + 0] + bbp[4 * ug + 0];
            float gf = Csm[b * CS + 4 * ug + 1] + x * wip[4 * ug + 1] + bbp[4 * ug + 1];
            float gg = Csm[b * CS + 4 * ug + 2] + x * wip[4 * ug + 2] + bbp[4 * ug + 2];
            float go = Csm[b * CS + 4 * ug + 3] + x * wip[4 * ug + 3] + bbp[4 * ug + 3];
            float cn = sigf(gf) * c_reg[u] + sigf(gi) * tanhf(gg);
            c_reg[u] = cn;
            float hv = sigf(go) * tanhf(cn);
            __nv_bfloat16 hv1 = __float2bfloat16(hv);
            __nv_bfloat16 hv2 = __float2bfloat16(hv - __bfloat162float(hv1));
            h1r[u] = __bfloat16_as_ushort(hv1);
            h2r[u] = __bfloat16_as_ushort(hv2);
            if (s == T_STEPS - 1) g_hT[b * HID + n0 + ug] = hv;
        }
        uint32_t p1[2], p2[2];
#pragma unroll
        for (int q = 0; q < 2; q++) {
            p1[q] = (uint32_t)h1r[2 * q] | ((uint32_t)h1r[2 * q + 1] << 16);
            p2[q] = (uint32_t)h2r[2 * q] | ((uint32_t)h2r[2 * q + 1] << 16);
        }
        *(uint2*)(&g_h1[(s + 1) & 1][b * HID + n0 + half * 4]) = make_uint2(p1[0], p1[1]);
        *(uint2*)(&g_h2[(s + 1) & 1][b * HID + n0 + half * 4]) = make_uint2(p2[0], p2[1]);

        // barriers #2..#513
        grid_barrier(tid, &bar_sense);
    }

    // ---- Final FC: CTA bb computes out[bb, 0..127] ----
    {
        int bb = blockIdx.x;
        float* hrow = (float*)(smem + OFF_A);
        ((float4*)hrow)[tid] = ((const float4*)(g_hT + bb * HID))[tid];
        __syncthreads();
        for (int o = wid; o < OUTF; o += 8) {
            const float* fw = fc_W + o * HID;
            float sum = 0.f;
            for (int kk = lane; kk < HID; kk += 32)
                sum += hrow[kk] * __ldg(&fw[kk]);
#pragma unroll
            for (int dd = 16; dd; dd >>= 1)
                sum += __shfl_xor_sync(0xffffffffu, sum, dd);
            if (lane == 0)
                out[bb * OUTF + o] = sum + fc_b[o];
        }
    }

    // barrier #514: restores g_sense to 0 for the next (graph-replayed) launch
    grid_barrier(tid, &bar_sense);
}

extern "C" void kernel_launch(void* const* d_in, const int* in_sizes, int n_in,
                              void* d_out, int out_size)
{
    const float* y_hist = (const float*)d_in[0];
    const float* W_ih   = (const float*)d_in[1];
    const float* W_hh   = (const float*)d_in[2];
    const float* b_ih   = (const float*)d_in[3];
    const float* b_hh   = (const float*)d_in[4];
    const float* fc_W   = (const float*)d_in[5];
    const float* fc_b   = (const float*)d_in[6];
    const float* h0     = (const float*)d_in[7];
    const float* c0     = (const float*)d_in[8];
    float* out = (float*)d_out;

    cudaFuncSetAttribute(lstm_kernel,
                         cudaFuncAttributeMaxDynamicSharedMemorySize, SMEM_BYTES);

    lstm_kernel<<<GRID, NTHR, SMEM_BYTES>>>(y_hist, W_ih, W_hh, b_ih, b_hh,
                                            fc_W, fc_b, h0, c0, out);
}

// round 7
// speedup vs baseline: 3.4485x; 1.0202x over previous
#include <cuda_runtime.h>
#include <cuda_bf16.h>
#include <math.h>
#include <stdint.h>

#define BATCH   128
#define T_STEPS 512
#define HID     1024
#define OUTF    128
#define GRID    128
#define NTHR    256
#define NC      32          // gate rows per CTA (8 units x 4 gates)
#define UPC     8
#define KCH     64          // k elems per chunk (128B rows)
#define NCHUNK  (HID / KCH) // 16
#define CS      34          // Csm row stride (floats) — MUST be even (float2 stores)

// ---- persistent device state (zero-init; even barrier count per launch
//      restores it, so graph replay is safe) ----
__device__ __nv_bfloat16 g_h1[2][BATCH * HID];
__device__ __nv_bfloat16 g_h2[2][BATCH * HID];
__device__ float         g_hT[BATCH * HID];
__device__ unsigned int  g_arrive;
__device__ volatile unsigned int g_sense;

// ---- smem layout (bytes) ----
#define OFF_BB 64                      // 32 floats: b_ih+b_hh
#define OFF_WI 192                     // 32 floats: w_ih
#define OFF_W1 1024                    // W1: 16 chunks x 4KB = 64KB
#define OFF_W2 (OFF_W1 + 65536)       // W2: 64KB
#define OFF_A  (OFF_W2 + 65536)       // A ring: 2 stages x (h1 16K + h2 16K)
#define OFF_C  (OFF_A + 65536)        // C scratch: 2 partials x 128*CS floats
#define SMEM_BYTES (OFF_C + 2 * BATCH * CS * 4)   // 232448 == sm_100 cap

__device__ __forceinline__ uint32_t smem_u32(const void* p) {
    return (uint32_t)__cvta_generic_to_shared(p);
}
__device__ __forceinline__ void cp16(uint32_t s, const void* g) {
    asm volatile("cp.async.cg.shared.global [%0], [%1], 16;" :: "r"(s), "l"(g));
}
__device__ __forceinline__ void ldm4(uint32_t r[4], uint32_t addr) {
    asm volatile("ldmatrix.sync.aligned.m8n8.x4.shared.b16 {%0,%1,%2,%3}, [%4];"
                 : "=r"(r[0]), "=r"(r[1]), "=r"(r[2]), "=r"(r[3]) : "r"(addr));
}
__device__ __forceinline__ void mma16816(float c[4], const uint32_t a[4],
                                         uint32_t b0, uint32_t b1) {
    asm volatile(
        "mma.sync.aligned.m16n8k16.row.col.f32.bf16.bf16.f32 "
        "{%0,%1,%2,%3},{%4,%5,%6,%7},{%8,%9},{%0,%1,%2,%3};"
        : "+f"(c[0]), "+f"(c[1]), "+f"(c[2]), "+f"(c[3])
        : "r"(a[0]), "r"(a[1]), "r"(a[2]), "r"(a[3]), "r"(b0), "r"(b1));
}
__device__ __forceinline__ uint32_t sw128(uint32_t off) {
    return off ^ ((off >> 3) & 0x70);
}
__device__ __forceinline__ float sigf(float x) { return 1.0f / (1.0f + expf(-x)); }

// Sense-reversing grid barrier; EVEN number of calls per launch returns
// g_sense to 0 (its static-init value).
__device__ __forceinline__ void grid_barrier(int tid, unsigned* local) {
    __syncthreads();
    if (tid == 0) {
        unsigned want = *local ^ 1u;
        *local = want;
        __threadfence();
        unsigned a = atomicAdd(&g_arrive, 1u);
        if (a == GRID - 1) {
            g_arrive = 0;
            __threadfence();
            g_sense = want;
        } else {
            while (g_sense != want) __nanosleep(32);
        }
        __threadfence();
    }
    __syncthreads();
}

__global__ void __launch_bounds__(NTHR, 1)
lstm_kernel(const float* __restrict__ y_hist,
            const float* __restrict__ W_ih,
            const float* __restrict__ W_hh,
            const float* __restrict__ b_ih,
            const float* __restrict__ b_hh,
            const float* __restrict__ fc_W,
            const float* __restrict__ fc_b,
            const float* __restrict__ h0,
            const float* __restrict__ c0,
            float* __restrict__ out)
{
    extern __shared__ char smem[];
    const uint32_t sb = smem_u32(smem);
    const int tid  = threadIdx.x;
    const int wid  = tid >> 5;
    const int lane = tid & 31;
    const int mw   = wid & 3;          // m-group: rows mw*32..+31
    const int kh   = wid >> 2;         // k-half: 0 or 1
    const int n0   = blockIdx.x * UPC;
    const int b    = tid & 127;        // batch row for epilogue
    const int half = tid >> 7;         // which 4 units this thread updates
    unsigned bar_sense = 0;

    // ---- Split h0 for OUR batch row into bf16 hi/lo ----
    {
        int bb = blockIdx.x;
        for (int e = tid; e < HID; e += NTHR) {
            float v = h0[bb * HID + e];
            __nv_bfloat16 a = __float2bfloat16(v);
            __nv_bfloat16 r = __float2bfloat16(v - __bfloat162float(a));
            g_h1[0][bb * HID + e] = a;
            g_h2[0][bb * HID + e] = r;
        }
    }

    // ---- One-time: W_hh slice -> bf16 hi/lo, SW128 chunk tiles in smem ----
    for (int e = tid; e < NC * HID; e += NTHR) {
        int lr = e >> 10, k = e & 1023;
        int u = lr >> 2, g = lr & 3;
        float w = W_hh[(g * HID + n0 + u) * HID + k];
        __nv_bfloat16 w1 = __float2bfloat16(w);
        __nv_bfloat16 w2 = __float2bfloat16(w - __bfloat162float(w1));
        int kc  = k >> 6;
        uint32_t off = (uint32_t)(lr * 128 + (k & 63) * 2);
        uint32_t sw  = sw128(off);
        *(__nv_bfloat16*)(smem + OFF_W1 + kc * 4096 + sw) = w1;
        *(__nv_bfloat16*)(smem + OFF_W2 + kc * 4096 + sw) = w2;
    }
    for (int e = tid; e < NC; e += NTHR) {
        int u = e >> 2, g = e & 3;
        int gr = g * HID + n0 + u;
        ((float*)(smem + OFF_BB))[e] = b_ih[gr] + b_hh[gr];
        ((float*)(smem + OFF_WI))[e] = W_ih[gr];
    }
    float c_reg[4];
#pragma unroll
    for (int u = 0; u < 4; u++)
        c_reg[u] = c0[b * HID + n0 + half * 4 + u];

    // barrier #1: h0 split visible grid-wide
    grid_barrier(tid, &bar_sense);

    float* Csm = (float*)(smem + OFF_C);
    const float* bbp = (const float*)(smem + OFF_BB);
    const float* wip = (const float*)(smem + OFF_WI);

    // ldmatrix lane address components
    const int arow = lane & 15;
    const int akb  = (lane >> 4) << 4;
    const int brow = (lane & 7) + ((lane & 16) >> 1);
    const int bkb  = (lane & 8) << 1;

    for (int s = 0; s < T_STEPS; s++) {
        const char* h1src = (const char*)g_h1[s & 1];
        const char* h2src = (const char*)g_h2[s & 1];
        float x = __ldg(&y_hist[b * T_STEPS + s]);

        // prologue: stage chunk 0 -> stage 0
#pragma unroll
        for (int part = 0; part < 2; part++) {
            const char* gp = part ? h2src : h1src;
            uint32_t abase = sb + OFF_A + part * 16384;
#pragma unroll
            for (int i = 0; i < 4; i++) {
                int f = i * NTHR + tid;
                int row = f >> 3, seg = f & 7;
                uint32_t off = (uint32_t)(row * 128 + seg * 16);
                cp16(abase + sw128(off), gp + row * 2048 + seg * 16);
            }
        }
        asm volatile("cp.async.commit_group;" ::: "memory");

        float acc[2][4][4];
#pragma unroll
        for (int mt = 0; mt < 2; mt++)
#pragma unroll
            for (int nt = 0; nt < 4; nt++)
#pragma unroll
                for (int q = 0; q < 4; q++)
                    acc[mt][nt][q] = 0.f;

        for (int kc = 0; kc < NCHUNK; kc++) {
            const int buf = kc & 1;
            // chunk kc's data arrived (only its group can be pending)
            asm volatile("cp.async.wait_group 0;" ::: "memory");
            __syncthreads();   // publish chunk kc; also: all ldsm on the other
                               // stage (iter kc-1) are done before we refill it

            const uint32_t a1b = sb + OFF_A + (buf * 2 + 0) * 16384;
            const uint32_t a2b = sb + OFF_A + (buf * 2 + 1) * 16384;
            const uint32_t w1b = sb + OFF_W1 + kc * 4096;
            const uint32_t w2b = sb + OFF_W2 + kc * 4096;

            // ---- t = 0 loads ----
            uint32_t a1[2][4], a2[2][4], bw1[2][4], bw2[2][4];
            {
                const int kbb = kh * 64;   // byte offset of this warp's k-half
#pragma unroll
                for (int mt = 0; mt < 2; mt++) {
                    uint32_t off = (uint32_t)((mw * 32 + mt * 16 + arow) * 128
                                              + kbb + akb);
                    ldm4(a1[mt], a1b + sw128(off));
                    ldm4(a2[mt], a2b + sw128(off));
                }
#pragma unroll
                for (int np = 0; np < 2; np++) {
                    uint32_t off = (uint32_t)((np * 16 + brow) * 128 + kbb + bkb);
                    ldm4(bw1[np], w1b + sw128(off));
                    ldm4(bw2[np], w2b + sw128(off));
                }
            }

            // refill the other stage with chunk kc+1 (overlaps t0/t1 compute)
            if (kc + 1 < NCHUNK) {
                int nb = (kc + 1) & 1;
#pragma unroll
                for (int part = 0; part < 2; part++) {
                    const char* gp = part ? h2src : h1src;
                    uint32_t abase = sb + OFF_A + (nb * 2 + part) * 16384;
#pragma unroll
                    for (int i = 0; i < 4; i++) {
                        int f = i * NTHR + tid;
                        int row = f >> 3, seg = f & 7;
                        uint32_t off = (uint32_t)(row * 128 + seg * 16);
                        cp16(abase + sw128(off),
                             gp + row * 2048 + (kc + 1) * 128 + seg * 16);
                    }
                }
                asm volatile("cp.async.commit_group;" ::: "memory");
            }

            // ---- t = 0 MMAs ----
#pragma unroll
            for (int mt = 0; mt < 2; mt++)
#pragma unroll
                for (int nt = 0; nt < 4; nt++) {
                    uint32_t b0 = bw1[nt >> 1][(nt & 1) * 2];
                    uint32_t b1 = bw1[nt >> 1][(nt & 1) * 2 + 1];
                    uint32_t c0f = bw2[nt >> 1][(nt & 1) * 2];
                    uint32_t c1f = bw2[nt >> 1][(nt & 1) * 2 + 1];
                    mma16816(acc[mt][nt], a1[mt], b0, b1);    // h1@W1
                    mma16816(acc[mt][nt], a1[mt], c0f, c1f);  // h1@W2
                    mma16816(acc[mt][nt], a2[mt], b0, b1);    // h2@W1
                }

            // ---- t = 1 ----
            {
                const int kbb = kh * 64 + 32;
#pragma unroll
                for (int mt = 0; mt < 2; mt++) {
                    uint32_t off = (uint32_t)((mw * 32 + mt * 16 + arow) * 128
                                              + kbb + akb);
                    ldm4(a1[mt], a1b + sw128(off));
                    ldm4(a2[mt], a2b + sw128(off));
                }
#pragma unroll
                for (int np = 0; np < 2; np++) {
                    uint32_t off = (uint32_t)((np * 16 + brow) * 128 + kbb + bkb);
                    ldm4(bw1[np], w1b + sw128(off));
                    ldm4(bw2[np], w2b + sw128(off));
                }
#pragma unroll
                for (int mt = 0; mt < 2; mt++)
#pragma unroll
                    for (int nt = 0; nt < 4; nt++) {
                        uint32_t b0 = bw1[nt >> 1][(nt & 1) * 2];
                        uint32_t b1 = bw1[nt >> 1][(nt & 1) * 2 + 1];
                        uint32_t c0f = bw2[nt >> 1][(nt & 1) * 2];
                        uint32_t c1f = bw2[nt >> 1][(nt & 1) * 2 + 1];
                        mma16816(acc[mt][nt], a1[mt], b0, b1);
                        mma16816(acc[mt][nt], a1[mt], c0f, c1f);
                        mma16816(acc[mt][nt], a2[mt], b0, b1);
                    }
            }
        }

        // ---- partial C fragments -> smem (region per k-half) ----
        {
            float* Cp = Csm + kh * (BATCH * CS);
#pragma unroll
            for (int mt = 0; mt < 2; mt++) {
                int r0 = mw * 32 + mt * 16 + (lane >> 2);
#pragma unroll
                for (int nt = 0; nt < 4; nt++) {
                    int col = nt * 8 + (lane & 3) * 2;
                    *(float2*)(Cp + r0 * CS + col) =
                        make_float2(acc[mt][nt][0], acc[mt][nt][1]);
                    *(float2*)(Cp + (r0 + 8) * CS + col) =
                        make_float2(acc[mt][nt][2], acc[mt][nt][3]);
                }
            }
        }
        __syncthreads();

        // ---- cell update: thread (b, half) owns batch row b, units half*4..+3 ----
        unsigned short h1r[4], h2r[4];
#pragma unroll
        for (int u = 0; u < 4; u++) {
            int ug = half * 4 + u;
            int c0i = b * CS + 4 * ug;
            int c1i = BATCH * CS + c0i;
            float gi = Csm[c0i + 0] + Csm[c1i + 0] + x * wip[4 * ug + 0] + bbp[4 * ug + 0];
            float gf = Csm[c0i + 1] + Csm[c1i + 1] + x * wip[4 * ug + 1] + bbp[4 * ug + 1];
            float gg = Csm[c0i + 2] + Csm[c1i + 2] + x * wip[4 * ug + 2] + bbp[4 * ug + 2];
            float go = Csm[c0i + 3] + Csm[c1i + 3] + x * wip[4 * ug + 3] + bbp[4 * ug + 3];
            float cn = sigf(gf) * c_reg[u] + sigf(gi) * tanhf(gg);
            c_reg[u] = cn;
            float hv = sigf(go) * tanhf(cn);
            __nv_bfloat16 hv1 = __float2bfloat16(hv);
            __nv_bfloat16 hv2 = __float2bfloat16(hv - __bfloat162float(hv1));
            h1r[u] = __bfloat16_as_ushort(hv1);
            h2r[u] = __bfloat16_as_ushort(hv2);
            if (s == T_STEPS - 1) g_hT[b * HID + n0 + ug] = hv;
        }
        uint32_t p1[2], p2[2];
#pragma unroll
        for (int q = 0; q < 2; q++) {
            p1[q] = (uint32_t)h1r[2 * q] | ((uint32_t)h1r[2 * q + 1] << 16);
            p2[q] = (uint32_t)h2r[2 * q] | ((uint32_t)h2r[2 * q + 1] << 16);
        }
        *(uint2*)(&g_h1[(s + 1) & 1][b * HID + n0 + half * 4]) = make_uint2(p1[0], p1[1]);
        *(uint2*)(&g_h2[(s + 1) & 1][b * HID + n0 + half * 4]) = make_uint2(p2[0], p2[1]);

        // barriers #2..#513
        grid_barrier(tid, &bar_sense);
    }

    // ---- Final FC: CTA bb computes out[bb, 0..127] ----
    {
        int bb = blockIdx.x;
        float* hrow = (float*)(smem + OFF_A);
        ((float4*)hrow)[tid] = ((const float4*)(g_hT + bb * HID))[tid];
        __syncthreads();
        for (int o = wid; o < OUTF; o += 8) {
            const float* fw = fc_W + o * HID;
            float sum = 0.f;
            for (int kk = lane; kk < HID; kk += 32)
                sum += hrow[kk] * __ldg(&fw[kk]);
#pragma unroll
            for (int dd = 16; dd; dd >>= 1)
                sum += __shfl_xor_sync(0xffffffffu, sum, dd);
            if (lane == 0)
                out[bb * OUTF + o] = sum + fc_b[o];
        }
    }

    // barrier #514: restores g_sense to 0 for graph replay
    grid_barrier(tid, &bar_sense);
}

extern "C" void kernel_launch(void* const* d_in, const int* in_sizes, int n_in,
                              void* d_out, int out_size)
{
    const float* y_hist = (const float*)d_in[0];
    const float* W_ih   = (const float*)d_in[1];
    const float* W_hh   = (const float*)d_in[2];
    const float* b_ih   = (const float*)d_in[3];
    const float* b_hh   = (const float*)d_in[4];
    const float* fc_W   = (const float*)d_in[5];
    const float* fc_b   = (const float*)d_in[6];
    const float* h0     = (const float*)d_in[7];
    const float* c0     = (const float*)d_in[8];
    float* out = (float*)d_out;

    cudaFuncSetAttribute(lstm_kernel,
                         cudaFuncAttributeMaxDynamicSharedMemorySize, SMEM_BYTES);

    lstm_kernel<<<GRID, NTHR, SMEM_BYTES>>>(y_hist, W_ih, W_hh, b_ih, b_hh,
                                            fc_W, fc_b, h0, c0, out);
}